// round 6
// baseline (speedup 1.0000x reference)
#include <cuda_runtime.h>
#include <math.h>

#define PTS    4096
#define BATCH  32
#define NB     256                       // x-buckets per (set,batch)
#define TPB    256                       // scan kernel threads
#define TPB_B  1024                      // bucket kernel threads
#define QTILES (PTS / TPB)               // 16 query tiles per (dir,batch)

// Bucket-ordered point sets, pre-scaled {-2x, -2y, -2z, |p|^2}.
__device__ float4 g_sA[BATCH * PTS];     // pred (set 0)
__device__ float4 g_sB[BATCH * PTS];     // gt   (set 1)
__device__ int    g_cdf[2 * BATCH * (NB + 1)];
__device__ float4 g_meta[2 * BATCH];     // {x0, w, invw, 0}

// ---------------------------------------------------------------------------
// Kernel 1: per (batch,set) bucket counting-sort by x. Grid (BATCH,2), 1024 thr.
// Also zeroes the output scalar (block (0,0)) before the scan kernel's atomics.
// ---------------------------------------------------------------------------
__global__ __launch_bounds__(TPB_B) void bucket_kernel(
    const float* __restrict__ pred, const float* __restrict__ gt,
    float* __restrict__ out)
{
    __shared__ unsigned hist[NB];
    __shared__ unsigned offs[NB];
    __shared__ unsigned wscan[8];
    __shared__ float    red[64];
    __shared__ float    sx0, sinvw, sw;

    const int b   = blockIdx.x;
    const int set = blockIdx.y;
    const int tid = threadIdx.x;
    const unsigned FULL = 0xFFFFFFFFu;
    const int lane = tid & 31, wid = tid >> 5;

    if (b == 0 && set == 0 && tid == 0) out[0] = 0.0f;

    const float* __restrict__ src = (set ? gt : pred) + (size_t)b * PTS * 3;

    // ---- pass 1: min/max of x ----
    float mn = 3.0e38f, mx = -3.0e38f;
    for (int i = tid; i < PTS; i += TPB_B) {
        float x = src[3 * i];
        mn = fminf(mn, x); mx = fmaxf(mx, x);
    }
    #pragma unroll
    for (int o = 16; o > 0; o >>= 1) {
        mn = fminf(mn, __shfl_xor_sync(FULL, mn, o));
        mx = fmaxf(mx, __shfl_xor_sync(FULL, mx, o));
    }
    if (lane == 0) { red[wid] = mn; red[32 + wid] = mx; }
    if (tid < NB) hist[tid] = 0;
    __syncthreads();
    if (tid == 0) {
        float a = red[0], c = red[32];
        #pragma unroll
        for (int i = 1; i < 32; i++) { a = fminf(a, red[i]); c = fmaxf(c, red[32 + i]); }
        float w = fmaxf(c - a, 1e-30f) / (float)NB;
        sx0 = a; sw = w; sinvw = 1.0f / w;
    }
    __syncthreads();
    const float x0 = sx0, invw = sinvw, w = sw;

    // ---- pass 2: histogram ----
    for (int i = tid; i < PTS; i += TPB_B) {
        float x = src[3 * i];
        int bk = (int)fminf(fmaxf((x - x0) * invw, 0.0f), (float)(NB - 1));
        atomicAdd(&hist[bk], 1u);
    }
    __syncthreads();

    // ---- exclusive scan over NB=256 (first 256 threads) ----
    if (tid < NB) {
        unsigned v = hist[tid];
        unsigned inc = v;
        #pragma unroll
        for (int o = 1; o < 32; o <<= 1) {
            unsigned n = __shfl_up_sync(FULL, inc, o);
            if (lane >= o) inc += n;
        }
        if (lane == 31) wscan[wid] = inc;
        __syncthreads();
        if (wid == 0 && lane < 8) {
            unsigned wv = wscan[lane];
            #pragma unroll
            for (int o = 1; o < 8; o <<= 1) {
                unsigned n = __shfl_up_sync(0xFFu, wv, o);
                if (lane >= o) wv += n;
            }
            wscan[lane] = wv;
        }
        __syncthreads();
        unsigned excl = inc - v + (wid ? wscan[wid - 1] : 0u);
        offs[tid] = excl;

        const int base = (set * BATCH + b) * (NB + 1);
        g_cdf[base + tid] = (int)excl;
        if (tid == 0) {
            g_cdf[base + NB] = PTS;
            g_meta[set * BATCH + b] = make_float4(x0, w, invw, 0.0f);
        }
    } else {
        __syncthreads();
        __syncthreads();
    }
    __syncthreads();

    // ---- pass 3: scatter (pre-scaled) ----
    float4* __restrict__ dst = (set ? g_sB : g_sA) + (size_t)b * PTS;
    for (int i = tid; i < PTS; i += TPB_B) {
        float x = src[3 * i], y = src[3 * i + 1], z = src[3 * i + 2];
        int bk = (int)fminf(fmaxf((x - x0) * invw, 0.0f), (float)(NB - 1));
        unsigned pos = atomicAdd(&offs[bk], 1u);
        dst[pos] = make_float4(-2.0f * x, -2.0f * y, -2.0f * z,
                               fmaf(x, x, fmaf(y, y, z * z)));
    }
}

// ---------------------------------------------------------------------------
// Kernel 2: two-phase windowed NN scan. Grid (QTILES, BATCH, 2).
//   dir 0: query = gt, target = pred ; dir 1: query = pred, target = gt.
// Phase 1: scan warp's query buckets +-1 -> upper bound d_ub per lane.
// Phase 2: scan the analytically derived flanks [BL..lo0) and (hi0..BR].
// All ranges warp-uniform; hot loops are guard-free and branch-free.
// ---------------------------------------------------------------------------
__global__ __launch_bounds__(TPB) void chamfer_scan_kernel(float* __restrict__ out)
{
    const int qt  = blockIdx.x;
    const int b   = blockIdx.y;
    const int dir = blockIdx.z;
    const int tid = threadIdx.x;
    const unsigned FULL = 0xFFFFFFFFu;
    const int lane = tid & 31;

    const int qset = dir ? 0 : 1;           // dir1: query pred
    const int tset = dir ? 1 : 0;
    const float4* __restrict__ qry = (qset ? g_sB : g_sA) + (size_t)b * PTS;
    const float4* __restrict__ tgt = (tset ? g_sB : g_sA) + (size_t)b * PTS;
    const int*    __restrict__ cdf = g_cdf + (tset * BATCH + b) * (NB + 1);

    const float4 meta = __ldg(&g_meta[tset * BATCH + b]);
    const float x0 = meta.x, invw = meta.z;

    // Query (stored scaled; recover coords).
    const float4 qp = __ldg(&qry[qt * TPB + tid]);
    const float px = -0.5f * qp.x, py = -0.5f * qp.y, pz = -0.5f * qp.z;
    const float p2 = qp.w;

    int qb = (int)fminf(fmaxf((px - x0) * invw, 0.0f), (float)(NB - 1));
    int bmin = qb, bmax = qb;
    #pragma unroll
    for (int o = 16; o > 0; o >>= 1) {
        bmin = min(bmin, __shfl_xor_sync(FULL, bmin, o));
        bmax = max(bmax, __shfl_xor_sync(FULL, bmax, o));
    }

    const int lo0 = max(bmin - 1, 0);
    const int hi0 = min(bmax + 1, NB - 1);
    const int s1  = __ldg(&cdf[lo0]);
    const int e1  = __ldg(&cdf[hi0 + 1]);

    float bt0 = 3.0e38f, bt1 = 3.0e38f, bt2 = 3.0e38f, bt3 = 3.0e38f;

    #define BODY(J, ACC) {                                                     \
        float4 g = __ldg(tgt + (J));                                           \
        ACC = fminf(ACC, fmaf(pz, g.z, fmaf(py, g.y, fmaf(px, g.x, g.w))));    \
    }
    #define SCAN_RANGE(LO, HI) {                                               \
        int j = (LO);                                                          \
        for (; j + 8 <= (HI); j += 8) {                                        \
            BODY(j + 0, bt0) BODY(j + 1, bt1) BODY(j + 2, bt2) BODY(j + 3, bt3)\
            BODY(j + 4, bt0) BODY(j + 5, bt1) BODY(j + 6, bt2) BODY(j + 7, bt3)\
        }                                                                      \
        for (; j < (HI); ++j) BODY(j, bt0)                                     \
    }

    // ---- Phase 1: central region ----
    SCAN_RANGE(s1, e1)

    // ---- Phase 2: analytic window from upper bound ----
    float bt  = fminf(fminf(bt0, bt1), fminf(bt2, bt3));
    float d   = sqrtf(fmaxf(bt + p2, 0.0f)) * 1.000002f;   // rounding slack

    // floorf then clamp in float (inf-safe), widen one bucket each side.
    float tl = floorf((px - d - x0) * invw) - 1.0f;
    float tr = floorf((px + d - x0) * invw) + 1.0f;
    int bl = (int)fminf(fmaxf(tl, 0.0f), (float)(NB - 1));
    int br = (int)fminf(fmaxf(tr, 0.0f), (float)(NB - 1));
    #pragma unroll
    for (int o = 16; o > 0; o >>= 1) {
        bl = min(bl, __shfl_xor_sync(FULL, bl, o));
        br = max(br, __shfl_xor_sync(FULL, br, o));
    }
    bl = min(bl, lo0);
    br = max(br, hi0);

    const int sL = __ldg(&cdf[bl]);          // left flank  [sL, s1)
    const int eR = __ldg(&cdf[br + 1]);      // right flank [e1, eR)
    SCAN_RANGE(sL, s1)
    SCAN_RANGE(e1, eR)

    #undef SCAN_RANGE
    #undef BODY

    bt = fminf(fminf(bt0, bt1), fminf(bt2, bt3));
    float dist = sqrtf(fmaxf(bt + p2, 1e-12f));

    // ---- Block sum reduction + single atomic into out ----
    #pragma unroll
    for (int o = 16; o > 0; o >>= 1)
        dist += __shfl_down_sync(FULL, dist, o);

    __shared__ float wsum[TPB / 32];
    const int wid = tid >> 5;
    if (lane == 0) wsum[wid] = dist;
    __syncthreads();
    if (tid < TPB / 32) {
        float v = wsum[tid];
        #pragma unroll
        for (int o = (TPB / 32) / 2; o > 0; o >>= 1)
            v += __shfl_down_sync(FULL, v, o, TPB / 32);
        if (tid == 0)
            atomicAdd(out, v * (1.0f / (float)(BATCH * PTS)));
    }
}

extern "C" void kernel_launch(void* const* d_in, const int* in_sizes, int n_in,
                              void* d_out, int out_size)
{
    (void)in_sizes; (void)n_in; (void)out_size;
    const float* pred = (const float*)d_in[0];
    const float* gt   = (const float*)d_in[1];
    float* out        = (float*)d_out;

    dim3 bgrid(BATCH, 2);
    bucket_kernel<<<bgrid, TPB_B>>>(pred, gt, out);

    dim3 sgrid(QTILES, BATCH, 2);
    chamfer_scan_kernel<<<sgrid, TPB>>>(out);
}

// round 7
// speedup vs baseline: 1.0856x; 1.0856x over previous
#include <cuda_runtime.h>
#include <math.h>

#define PTS    4096
#define BATCH  32
#define NB     256                       // x-buckets per (set,batch)
#define TPB    256                       // scan kernel threads
#define TPB_B  1024                      // bucket kernel threads
#define QTILES (PTS / TPB)               // 16 query tiles per (dir,batch)
#define SMEM_SCAN (PTS * 16)             // 64KB dynamic: staged targets

// Bucket-ordered point sets, pre-scaled {-2x, -2y, -2z, |p|^2}.
__device__ float4 g_sA[BATCH * PTS];     // pred (set 0)
__device__ float4 g_sB[BATCH * PTS];     // gt   (set 1)
__device__ int    g_cdf[2 * BATCH * (NB + 1)];
__device__ float4 g_meta[2 * BATCH];     // {x0, w, invw, 0}

// ---------------------------------------------------------------------------
// Kernel 1: per (batch,set) bucket counting-sort by x. Grid (BATCH,2), 1024 thr.
// Also zeroes the output scalar (block (0,0)) before the scan kernel's atomics.
// ---------------------------------------------------------------------------
__global__ __launch_bounds__(TPB_B) void bucket_kernel(
    const float* __restrict__ pred, const float* __restrict__ gt,
    float* __restrict__ out)
{
    __shared__ unsigned hist[NB];
    __shared__ unsigned offs[NB];
    __shared__ unsigned wscan[8];
    __shared__ float    red[64];
    __shared__ float    sx0, sinvw, sw;

    const int b   = blockIdx.x;
    const int set = blockIdx.y;
    const int tid = threadIdx.x;
    const unsigned FULL = 0xFFFFFFFFu;
    const int lane = tid & 31, wid = tid >> 5;

    if (b == 0 && set == 0 && tid == 0) out[0] = 0.0f;

    const float* __restrict__ src = (set ? gt : pred) + (size_t)b * PTS * 3;

    // ---- pass 1: min/max of x ----
    float mn = 3.0e38f, mx = -3.0e38f;
    for (int i = tid; i < PTS; i += TPB_B) {
        float x = src[3 * i];
        mn = fminf(mn, x); mx = fmaxf(mx, x);
    }
    #pragma unroll
    for (int o = 16; o > 0; o >>= 1) {
        mn = fminf(mn, __shfl_xor_sync(FULL, mn, o));
        mx = fmaxf(mx, __shfl_xor_sync(FULL, mx, o));
    }
    if (lane == 0) { red[wid] = mn; red[32 + wid] = mx; }
    if (tid < NB) hist[tid] = 0;
    __syncthreads();
    if (tid == 0) {
        float a = red[0], c = red[32];
        #pragma unroll
        for (int i = 1; i < 32; i++) { a = fminf(a, red[i]); c = fmaxf(c, red[32 + i]); }
        float w = fmaxf(c - a, 1e-30f) / (float)NB;
        sx0 = a; sw = w; sinvw = 1.0f / w;
    }
    __syncthreads();
    const float x0 = sx0, invw = sinvw, w = sw;

    // ---- pass 2: histogram ----
    for (int i = tid; i < PTS; i += TPB_B) {
        float x = src[3 * i];
        int bk = (int)fminf(fmaxf((x - x0) * invw, 0.0f), (float)(NB - 1));
        atomicAdd(&hist[bk], 1u);
    }
    __syncthreads();

    // ---- exclusive scan over NB=256 (first 256 threads) ----
    if (tid < NB) {
        unsigned v = hist[tid];
        unsigned inc = v;
        #pragma unroll
        for (int o = 1; o < 32; o <<= 1) {
            unsigned n = __shfl_up_sync(FULL, inc, o);
            if (lane >= o) inc += n;
        }
        if (lane == 31) wscan[wid] = inc;
        __syncthreads();
        if (wid == 0 && lane < 8) {
            unsigned wv = wscan[lane];
            #pragma unroll
            for (int o = 1; o < 8; o <<= 1) {
                unsigned n = __shfl_up_sync(0xFFu, wv, o);
                if (lane >= o) wv += n;
            }
            wscan[lane] = wv;
        }
        __syncthreads();
        unsigned excl = inc - v + (wid ? wscan[wid - 1] : 0u);
        offs[tid] = excl;

        const int base = (set * BATCH + b) * (NB + 1);
        g_cdf[base + tid] = (int)excl;
        if (tid == 0) {
            g_cdf[base + NB] = PTS;
            g_meta[set * BATCH + b] = make_float4(x0, w, invw, 0.0f);
        }
    } else {
        __syncthreads();
        __syncthreads();
    }
    __syncthreads();

    // ---- pass 3: scatter (pre-scaled) ----
    float4* __restrict__ dst = (set ? g_sB : g_sA) + (size_t)b * PTS;
    for (int i = tid; i < PTS; i += TPB_B) {
        float x = src[3 * i], y = src[3 * i + 1], z = src[3 * i + 2];
        int bk = (int)fminf(fmaxf((x - x0) * invw, 0.0f), (float)(NB - 1));
        unsigned pos = atomicAdd(&offs[bk], 1u);
        dst[pos] = make_float4(-2.0f * x, -2.0f * y, -2.0f * z,
                               fmaf(x, x, fmaf(y, y, z * z)));
    }
}

// ---------------------------------------------------------------------------
// Kernel 2: two-phase windowed NN scan over SMEM-staged targets.
// Grid (QTILES, BATCH, 2). dir 0: query=gt,target=pred; dir 1: reverse.
// Phase 1: scan warp-union query buckets +-1 -> per-lane upper bound.
// Phase 2: scan analytic flanks derived from the bound. Hot loops are
// guard-free LDS.128 + 3 FFMA + FMNMX; ranges warp-uniform (no divergence).
// ---------------------------------------------------------------------------
__global__ __launch_bounds__(TPB) void chamfer_scan_kernel(float* __restrict__ out)
{
    extern __shared__ float4 st[];          // 4096 scaled targets
    __shared__ int   scdf[NB + 1];
    __shared__ float smeta[2];              // x0, invw of target set

    const int qt  = blockIdx.x;
    const int b   = blockIdx.y;
    const int dir = blockIdx.z;
    const int tid = threadIdx.x;
    const unsigned FULL = 0xFFFFFFFFu;
    const int lane = tid & 31;

    const int qset = dir ? 0 : 1;           // dir1: query pred
    const int tset = dir ? 1 : 0;
    const float4* __restrict__ qry = (qset ? g_sB : g_sA) + (size_t)b * PTS;
    const float4* __restrict__ tgt = (tset ? g_sB : g_sA) + (size_t)b * PTS;

    for (int i = tid; i < PTS; i += TPB) st[i] = tgt[i];
    for (int i = tid; i < NB + 1; i += TPB)
        scdf[i] = g_cdf[(tset * BATCH + b) * (NB + 1) + i];
    if (tid == 0) {
        float4 m = g_meta[tset * BATCH + b];
        smeta[0] = m.x; smeta[1] = m.z;
    }
    __syncthreads();
    const float x0 = smeta[0], invw = smeta[1];

    // Query (stored scaled; recover coords).
    const float4 qp = __ldg(&qry[qt * TPB + tid]);
    const float px = -0.5f * qp.x, py = -0.5f * qp.y, pz = -0.5f * qp.z;
    const float p2 = qp.w;

    int qb = (int)fminf(fmaxf((px - x0) * invw, 0.0f), (float)(NB - 1));
    int bmin = qb, bmax = qb;
    #pragma unroll
    for (int o = 16; o > 0; o >>= 1) {
        bmin = min(bmin, __shfl_xor_sync(FULL, bmin, o));
        bmax = max(bmax, __shfl_xor_sync(FULL, bmax, o));
    }

    const int lo0 = max(bmin - 1, 0);
    const int hi0 = min(bmax + 1, NB - 1);
    const int s1  = scdf[lo0];
    const int e1  = scdf[hi0 + 1];

    float bt0 = 3.0e38f, bt1 = 3.0e38f, bt2 = 3.0e38f, bt3 = 3.0e38f;

    #define BODY(J, ACC) {                                                     \
        float4 g = st[(J)];                                                    \
        ACC = fminf(ACC, fmaf(pz, g.z, fmaf(py, g.y, fmaf(px, g.x, g.w))));    \
    }
    #define SCAN_RANGE(LO, HI) {                                               \
        int j = (LO);                                                          \
        for (; j + 8 <= (HI); j += 8) {                                        \
            BODY(j + 0, bt0) BODY(j + 1, bt1) BODY(j + 2, bt2) BODY(j + 3, bt3)\
            BODY(j + 4, bt0) BODY(j + 5, bt1) BODY(j + 6, bt2) BODY(j + 7, bt3)\
        }                                                                      \
        for (; j < (HI); ++j) BODY(j, bt0)                                     \
    }

    // ---- Phase 1: central region ----
    SCAN_RANGE(s1, e1)

    // ---- Phase 2: analytic window from upper bound ----
    float bt  = fminf(fminf(bt0, bt1), fminf(bt2, bt3));
    float d   = sqrtf(fmaxf(bt + p2, 0.0f)) * 1.000002f;   // rounding slack

    float tl = floorf((px - d - x0) * invw) - 1.0f;
    float tr = floorf((px + d - x0) * invw) + 1.0f;
    int bl = (int)fminf(fmaxf(tl, 0.0f), (float)(NB - 1));
    int br = (int)fminf(fmaxf(tr, 0.0f), (float)(NB - 1));
    #pragma unroll
    for (int o = 16; o > 0; o >>= 1) {
        bl = min(bl, __shfl_xor_sync(FULL, bl, o));
        br = max(br, __shfl_xor_sync(FULL, br, o));
    }
    bl = min(bl, lo0);
    br = max(br, hi0);

    const int sL = scdf[bl];                 // left flank  [sL, s1)
    const int eR = scdf[br + 1];             // right flank [e1, eR)
    SCAN_RANGE(sL, s1)
    SCAN_RANGE(e1, eR)

    #undef SCAN_RANGE
    #undef BODY

    bt = fminf(fminf(bt0, bt1), fminf(bt2, bt3));
    float dist = sqrtf(fmaxf(bt + p2, 1e-12f));

    // ---- Block sum reduction + single atomic into out ----
    #pragma unroll
    for (int o = 16; o > 0; o >>= 1)
        dist += __shfl_down_sync(FULL, dist, o);

    __shared__ float wsum[TPB / 32];
    const int wid = tid >> 5;
    if (lane == 0) wsum[wid] = dist;
    __syncthreads();
    if (tid < TPB / 32) {
        float v = wsum[tid];
        #pragma unroll
        for (int o = (TPB / 32) / 2; o > 0; o >>= 1)
            v += __shfl_down_sync(FULL, v, o, TPB / 32);
        if (tid == 0)
            atomicAdd(out, v * (1.0f / (float)(BATCH * PTS)));
    }
}

extern "C" void kernel_launch(void* const* d_in, const int* in_sizes, int n_in,
                              void* d_out, int out_size)
{
    (void)in_sizes; (void)n_in; (void)out_size;
    const float* pred = (const float*)d_in[0];
    const float* gt   = (const float*)d_in[1];
    float* out        = (float*)d_out;

    cudaFuncSetAttribute(chamfer_scan_kernel,
                         cudaFuncAttributeMaxDynamicSharedMemorySize, SMEM_SCAN);

    dim3 bgrid(BATCH, 2);
    bucket_kernel<<<bgrid, TPB_B>>>(pred, gt, out);

    dim3 sgrid(QTILES, BATCH, 2);
    chamfer_scan_kernel<<<sgrid, TPB, SMEM_SCAN>>>(out);
}

// round 8
// speedup vs baseline: 1.2351x; 1.1377x over previous
#include <cuda_runtime.h>
#include <math.h>

#define PTS    4096
#define BATCH  32
#define NBX    64
#define NBY    64
#define NCF    (NBX * NBY)              // 4096 fine cells (targets)
#define NCC    128                      // 16x8 coarse cells (queries)
#define TPB    256
#define TPB_B  1024
#define QTILES (PTS / TPB)              // 16

// Per (set, batch): fine-ordered targets, coarse-ordered queries, fine cdf.
// Points stored pre-scaled {-2x, -2y, -2z, |p|^2}.
__device__ float4 g_fine  [2 * BATCH * PTS];
__device__ float4 g_coarse[2 * BATCH * PTS];
__device__ int    g_cdfF  [2 * BATCH * (NCF + 1)];
__device__ float4 g_meta  [2 * BATCH];   // {x0, invwx, y0, invwy}

__device__ __forceinline__ int coarse_cell(int cx, int cy) {
    int cx2 = cx >> 2, cy2 = cy >> 3;
    cy2 = (cx2 & 1) ? (7 - cy2) : cy2;   // serpentine: adjacent warps stay adjacent
    return cx2 * 8 + cy2;
}

// ---------------------------------------------------------------------------
// Kernel 1: per (batch,set) 2-D counting sorts. Grid (BATCH, 2), 1024 threads.
// Builds fine ordering + cdf and coarse ordering. Zeroes out[0].
// ---------------------------------------------------------------------------
__global__ __launch_bounds__(TPB_B) void build_kernel(
    const float* __restrict__ pred, const float* __restrict__ gt,
    float* __restrict__ out)
{
    __shared__ unsigned hist[NCF];       // 16 KB
    __shared__ unsigned offs[NCF];       // 16 KB
    __shared__ unsigned histc[NCC];
    __shared__ unsigned offsc[NCC];
    __shared__ unsigned wscan[32];
    __shared__ unsigned wscanC[4];
    __shared__ float    red[128];
    __shared__ float    sm[4];

    const int b = blockIdx.x, set = blockIdx.y, tid = threadIdx.x;
    const int lane = tid & 31, wid = tid >> 5;
    const unsigned FULL = 0xFFFFFFFFu;

    if (b == 0 && set == 0 && tid == 0) out[0] = 0.0f;

    const float* __restrict__ src = (set ? gt : pred) + (size_t)b * PTS * 3;

    // ---- pass 1: bbox of (x, y) ----
    float mnx = 3e38f, mxx = -3e38f, mny = 3e38f, mxy = -3e38f;
    for (int i = tid; i < PTS; i += TPB_B) {
        float x = src[3 * i], y = src[3 * i + 1];
        mnx = fminf(mnx, x); mxx = fmaxf(mxx, x);
        mny = fminf(mny, y); mxy = fmaxf(mxy, y);
    }
    #pragma unroll
    for (int o = 16; o > 0; o >>= 1) {
        mnx = fminf(mnx, __shfl_xor_sync(FULL, mnx, o));
        mxx = fmaxf(mxx, __shfl_xor_sync(FULL, mxx, o));
        mny = fminf(mny, __shfl_xor_sync(FULL, mny, o));
        mxy = fmaxf(mxy, __shfl_xor_sync(FULL, mxy, o));
    }
    if (lane == 0) { red[wid] = mnx; red[32 + wid] = mxx; red[64 + wid] = mny; red[96 + wid] = mxy; }
    for (int i = tid; i < NCF; i += TPB_B) hist[i] = 0;
    if (tid < NCC) histc[tid] = 0;
    __syncthreads();
    if (tid == 0) {
        float a = red[0], c = red[32], e = red[64], f = red[96];
        #pragma unroll
        for (int i = 1; i < 32; i++) {
            a = fminf(a, red[i]);      c = fmaxf(c, red[32 + i]);
            e = fminf(e, red[64 + i]); f = fmaxf(f, red[96 + i]);
        }
        sm[0] = a; sm[1] = (float)NBX / fmaxf(c - a, 1e-30f);
        sm[2] = e; sm[3] = (float)NBY / fmaxf(f - e, 1e-30f);
        g_meta[set * BATCH + b] = make_float4(sm[0], sm[1], sm[2], sm[3]);
    }
    __syncthreads();
    const float x0 = sm[0], invwx = sm[1], y0 = sm[2], invwy = sm[3];

    // ---- pass 2: fine + coarse histograms ----
    for (int i = tid; i < PTS; i += TPB_B) {
        float x = src[3 * i], y = src[3 * i + 1];
        int cx = (int)fminf(fmaxf((x - x0) * invwx, 0.0f), (float)(NBX - 1));
        int cy = (int)fminf(fmaxf((y - y0) * invwy, 0.0f), (float)(NBY - 1));
        atomicAdd(&hist[cx * NBY + cy], 1u);
        atomicAdd(&histc[coarse_cell(cx, cy)], 1u);
    }
    __syncthreads();

    // ---- fine exclusive scan over 4096 (4 per thread) ----
    unsigned a0 = hist[4 * tid], a1 = hist[4 * tid + 1];
    unsigned a2 = hist[4 * tid + 2], a3 = hist[4 * tid + 3];
    unsigned s = a0 + a1 + a2 + a3;
    unsigned inc = s;
    #pragma unroll
    for (int o = 1; o < 32; o <<= 1) {
        unsigned n = __shfl_up_sync(FULL, inc, o);
        if (lane >= o) inc += n;
    }
    if (lane == 31) wscan[wid] = inc;
    __syncthreads();
    if (wid == 0) {
        unsigned wv = wscan[lane];
        #pragma unroll
        for (int o = 1; o < 32; o <<= 1) {
            unsigned n = __shfl_up_sync(FULL, wv, o);
            if (lane >= o) wv += n;
        }
        wscan[lane] = wv;
    }
    __syncthreads();
    unsigned excl = inc - s + (wid ? wscan[wid - 1] : 0u);
    const int base = (set * BATCH + b) * (NCF + 1);
    unsigned o0 = excl, o1 = excl + a0, o2 = o1 + a1, o3 = o2 + a2;
    offs[4 * tid] = o0; offs[4 * tid + 1] = o1; offs[4 * tid + 2] = o2; offs[4 * tid + 3] = o3;
    g_cdfF[base + 4 * tid]     = (int)o0;
    g_cdfF[base + 4 * tid + 1] = (int)o1;
    g_cdfF[base + 4 * tid + 2] = (int)o2;
    g_cdfF[base + 4 * tid + 3] = (int)o3;
    if (tid == 0) g_cdfF[base + NCF] = PTS;

    // ---- coarse exclusive scan over 128 (warps 0-3) ----
    unsigned s2 = 0, inc2 = 0;
    if (tid < NCC) {
        s2 = histc[tid]; inc2 = s2;
        #pragma unroll
        for (int o = 1; o < 32; o <<= 1) {
            unsigned n = __shfl_up_sync(FULL, inc2, o);
            if (lane >= o) inc2 += n;
        }
        if (lane == 31) wscanC[wid] = inc2;
    }
    __syncthreads();
    if (tid == 0) {
        unsigned r = 0;
        #pragma unroll
        for (int k = 0; k < 4; k++) { unsigned t = wscanC[k]; wscanC[k] = r; r += t; }
    }
    __syncthreads();
    if (tid < NCC) offsc[tid] = inc2 - s2 + wscanC[wid];
    __syncthreads();

    // ---- pass 3: scatter to fine and coarse orderings (pre-scaled) ----
    float4* __restrict__ dstF = g_fine   + (size_t)(set * BATCH + b) * PTS;
    float4* __restrict__ dstC = g_coarse + (size_t)(set * BATCH + b) * PTS;
    for (int i = tid; i < PTS; i += TPB_B) {
        float x = src[3 * i], y = src[3 * i + 1], z = src[3 * i + 2];
        int cx = (int)fminf(fmaxf((x - x0) * invwx, 0.0f), (float)(NBX - 1));
        int cy = (int)fminf(fmaxf((y - y0) * invwy, 0.0f), (float)(NBY - 1));
        float4 v = make_float4(-2.0f * x, -2.0f * y, -2.0f * z,
                               fmaf(x, x, fmaf(y, y, z * z)));
        unsigned pF = atomicAdd(&offs[cx * NBY + cy], 1u);
        dstF[pF] = v;
        unsigned pC = atomicAdd(&offsc[coarse_cell(cx, cy)], 1u);
        dstC[pC] = v;
    }
}

// ---------------------------------------------------------------------------
// Kernel 2: 2-D windowed NN scan. Grid (QTILES, BATCH, 2).
//   dir 0: query = gt, target = pred ; dir 1: query = pred, target = gt.
// Phase 1: scan warp-bbox +-1 x / +-2 y cells -> per-lane upper bound d.
// Phase 2: scan cells in [bbox +- warp-max d] (x AND y) -> exact NN.
// No smem, no syncthreads until the final reduction; all ranges warp-uniform.
// ---------------------------------------------------------------------------
__global__ __launch_bounds__(TPB) void chamfer_scan_kernel(float* __restrict__ out)
{
    const int qt = blockIdx.x, b = blockIdx.y, dir = blockIdx.z;
    const int tid = threadIdx.x;
    const unsigned FULL = 0xFFFFFFFFu;
    const int lane = tid & 31;

    const int qset = dir ? 0 : 1;
    const int tset = dir ? 1 : 0;
    const float4* __restrict__ qry = g_coarse + (size_t)(qset * BATCH + b) * PTS;
    const float4* __restrict__ tgt = g_fine   + (size_t)(tset * BATCH + b) * PTS;
    const int*    __restrict__ cdf = g_cdfF + (tset * BATCH + b) * (NCF + 1);

    const float4 m = __ldg(&g_meta[tset * BATCH + b]);
    const float x0 = m.x, invwx = m.y, y0 = m.z, invwy = m.w;

    const float4 qp = __ldg(&qry[qt * TPB + tid]);
    const float px = -0.5f * qp.x, py = -0.5f * qp.y, pz = -0.5f * qp.z;
    const float p2 = qp.w;

    // Warp bbox of queries.
    float qxl = px, qxh = px, qyl = py, qyh = py;
    #pragma unroll
    for (int o = 16; o > 0; o >>= 1) {
        qxl = fminf(qxl, __shfl_xor_sync(FULL, qxl, o));
        qxh = fmaxf(qxh, __shfl_xor_sync(FULL, qxh, o));
        qyl = fminf(qyl, __shfl_xor_sync(FULL, qyl, o));
        qyh = fmaxf(qyh, __shfl_xor_sync(FULL, qyh, o));
    }

    #define CLX(v) (int)fminf(fmaxf((v), 0.0f), (float)(NBX - 1))
    #define CLY(v) (int)fminf(fmaxf((v), 0.0f), (float)(NBY - 1))

    float bt0 = 3e38f, bt1 = 3e38f, bt2 = 3e38f, bt3 = 3e38f;

    #define BODY(J, ACC) {                                                     \
        float4 g = __ldg(tgt + (J));                                           \
        ACC = fminf(ACC, fmaf(pz, g.z, fmaf(py, g.y, fmaf(px, g.x, g.w))));    \
    }
    #define SCAN_RANGE(LO, HI) {                                               \
        int j = (LO);                                                          \
        for (; j + 4 <= (HI); j += 4) {                                        \
            BODY(j + 0, bt0) BODY(j + 1, bt1) BODY(j + 2, bt2) BODY(j + 3, bt3)\
        }                                                                      \
        for (; j < (HI); ++j) BODY(j, bt0)                                     \
    }

    // ---- Phase 1: neighborhood of warp bbox ----
    {
        int xl = CLX((qxl - x0) * invwx - 1.0f);
        int xh = CLX((qxh - x0) * invwx + 1.0f);
        int yl = CLY((qyl - y0) * invwy - 2.0f);
        int yh = CLY((qyh - y0) * invwy + 2.0f);
        for (int bx = xl; bx <= xh; ++bx) {
            int s = __ldg(&cdf[bx * NBY + yl]);
            int e = __ldg(&cdf[bx * NBY + yh + 1]);
            SCAN_RANGE(s, e)
        }
    }

    // ---- Phase 2: certified window from warp-max upper bound ----
    float bt = fminf(fminf(bt0, bt1), fminf(bt2, bt3));
    float d  = sqrtf(fmaxf(bt + p2, 0.0f)) * 1.000002f;
    float dmax = d;
    #pragma unroll
    for (int o = 16; o > 0; o >>= 1)
        dmax = fmaxf(dmax, __shfl_xor_sync(FULL, dmax, o));

    {
        int Xl = CLX(floorf((qxl - dmax - x0) * invwx) - 1.0f);
        int Xh = CLX(floorf((qxh + dmax - x0) * invwx) + 1.0f);
        int Yl = CLY(floorf((qyl - dmax - y0) * invwy) - 1.0f);
        int Yh = CLY(floorf((qyh + dmax - y0) * invwy) + 1.0f);
        for (int bx = Xl; bx <= Xh; ++bx) {
            int s = __ldg(&cdf[bx * NBY + Yl]);
            int e = __ldg(&cdf[bx * NBY + Yh + 1]);
            SCAN_RANGE(s, e)
        }
    }
    #undef SCAN_RANGE
    #undef BODY
    #undef CLX
    #undef CLY

    bt = fminf(fminf(bt0, bt1), fminf(bt2, bt3));
    float dist = sqrtf(fmaxf(bt + p2, 1e-12f));

    // ---- Block sum reduction + single atomic into out ----
    #pragma unroll
    for (int o = 16; o > 0; o >>= 1)
        dist += __shfl_down_sync(FULL, dist, o);

    __shared__ float wsum[TPB / 32];
    const int wid = tid >> 5;
    if (lane == 0) wsum[wid] = dist;
    __syncthreads();
    if (tid < TPB / 32) {
        float v = wsum[tid];
        #pragma unroll
        for (int o = (TPB / 32) / 2; o > 0; o >>= 1)
            v += __shfl_down_sync(FULL, v, o, TPB / 32);
        if (tid == 0)
            atomicAdd(out, v * (1.0f / (float)(BATCH * PTS)));
    }
}

extern "C" void kernel_launch(void* const* d_in, const int* in_sizes, int n_in,
                              void* d_out, int out_size)
{
    (void)in_sizes; (void)n_in; (void)out_size;
    const float* pred = (const float*)d_in[0];
    const float* gt   = (const float*)d_in[1];
    float* out        = (float*)d_out;

    dim3 bgrid(BATCH, 2);
    build_kernel<<<bgrid, TPB_B>>>(pred, gt, out);

    dim3 sgrid(QTILES, BATCH, 2);
    chamfer_scan_kernel<<<sgrid, TPB>>>(out);
}

// round 9
// speedup vs baseline: 1.8204x; 1.4740x over previous
#include <cuda_runtime.h>
#include <math.h>

#define PTS    4096
#define BATCH  32
#define NBX    32
#define NBY    32
#define NCF    (NBX * NBY)              // 1024 fine cells (~4 pts/cell)
#define NCC    128                      // 16x8 coarse cells (queries)
#define TPB    256
#define TPB_B  1024
#define QTILES (PTS / TPB)              // 16
#define SMEM_SCAN (PTS * 16)            // 64KB dynamic: staged targets

// Per (set, batch): fine-ordered targets, coarse-ordered queries, fine cdf.
// Points stored pre-scaled {-2x, -2y, -2z, |p|^2}.
__device__ float4 g_fine  [2 * BATCH * PTS];
__device__ float4 g_coarse[2 * BATCH * PTS];
__device__ int    g_cdfF  [2 * BATCH * (NCF + 1)];
__device__ float4 g_meta  [2 * BATCH];   // {x0, invwx, y0, invwy}

__device__ __forceinline__ int coarse_cell(int cx, int cy) {
    int cx2 = cx >> 1, cy2 = cy >> 2;    // 16 x 8
    cy2 = (cx2 & 1) ? (7 - cy2) : cy2;   // serpentine
    return cx2 * 8 + cy2;
}

// ---------------------------------------------------------------------------
// Kernel 1: per (batch,set) 2-D counting sorts. Grid (BATCH, 2), 1024 threads.
// ---------------------------------------------------------------------------
__global__ __launch_bounds__(TPB_B) void build_kernel(
    const float* __restrict__ pred, const float* __restrict__ gt,
    float* __restrict__ out)
{
    __shared__ unsigned hist[NCF];
    __shared__ unsigned offs[NCF];
    __shared__ unsigned histc[NCC];
    __shared__ unsigned offsc[NCC];
    __shared__ unsigned wscan[32];
    __shared__ unsigned wscanC[4];
    __shared__ float    red[128];
    __shared__ float    sm[4];

    const int b = blockIdx.x, set = blockIdx.y, tid = threadIdx.x;
    const int lane = tid & 31, wid = tid >> 5;
    const unsigned FULL = 0xFFFFFFFFu;

    if (b == 0 && set == 0 && tid == 0) out[0] = 0.0f;

    const float* __restrict__ src = (set ? gt : pred) + (size_t)b * PTS * 3;

    // ---- pass 1: bbox of (x, y) ----
    float mnx = 3e38f, mxx = -3e38f, mny = 3e38f, mxy = -3e38f;
    for (int i = tid; i < PTS; i += TPB_B) {
        float x = src[3 * i], y = src[3 * i + 1];
        mnx = fminf(mnx, x); mxx = fmaxf(mxx, x);
        mny = fminf(mny, y); mxy = fmaxf(mxy, y);
    }
    #pragma unroll
    for (int o = 16; o > 0; o >>= 1) {
        mnx = fminf(mnx, __shfl_xor_sync(FULL, mnx, o));
        mxx = fmaxf(mxx, __shfl_xor_sync(FULL, mxx, o));
        mny = fminf(mny, __shfl_xor_sync(FULL, mny, o));
        mxy = fmaxf(mxy, __shfl_xor_sync(FULL, mxy, o));
    }
    if (lane == 0) { red[wid] = mnx; red[32 + wid] = mxx; red[64 + wid] = mny; red[96 + wid] = mxy; }
    if (tid < NCF) hist[tid] = 0;
    if (tid < NCC) histc[tid] = 0;
    __syncthreads();
    if (tid == 0) {
        float a = red[0], c = red[32], e = red[64], f = red[96];
        #pragma unroll
        for (int i = 1; i < 32; i++) {
            a = fminf(a, red[i]);      c = fmaxf(c, red[32 + i]);
            e = fminf(e, red[64 + i]); f = fmaxf(f, red[96 + i]);
        }
        sm[0] = a; sm[1] = (float)NBX / fmaxf(c - a, 1e-30f);
        sm[2] = e; sm[3] = (float)NBY / fmaxf(f - e, 1e-30f);
        g_meta[set * BATCH + b] = make_float4(sm[0], sm[1], sm[2], sm[3]);
    }
    __syncthreads();
    const float x0 = sm[0], invwx = sm[1], y0 = sm[2], invwy = sm[3];

    // ---- pass 2: fine + coarse histograms ----
    for (int i = tid; i < PTS; i += TPB_B) {
        float x = src[3 * i], y = src[3 * i + 1];
        int cx = (int)fminf(fmaxf((x - x0) * invwx, 0.0f), (float)(NBX - 1));
        int cy = (int)fminf(fmaxf((y - y0) * invwy, 0.0f), (float)(NBY - 1));
        atomicAdd(&hist[cx * NBY + cy], 1u);
        atomicAdd(&histc[coarse_cell(cx, cy)], 1u);
    }
    __syncthreads();

    // ---- fine exclusive scan over 1024 (1 per thread) ----
    unsigned v = (tid < NCF) ? hist[tid] : 0u;
    unsigned inc = v;
    #pragma unroll
    for (int o = 1; o < 32; o <<= 1) {
        unsigned n = __shfl_up_sync(FULL, inc, o);
        if (lane >= o) inc += n;
    }
    if (lane == 31) wscan[wid] = inc;
    __syncthreads();
    if (wid == 0) {
        unsigned wv = wscan[lane];
        #pragma unroll
        for (int o = 1; o < 32; o <<= 1) {
            unsigned n = __shfl_up_sync(FULL, wv, o);
            if (lane >= o) wv += n;
        }
        wscan[lane] = wv;
    }
    __syncthreads();
    const int base = (set * BATCH + b) * (NCF + 1);
    if (tid < NCF) {
        unsigned excl = inc - v + (wid ? wscan[wid - 1] : 0u);
        offs[tid] = excl;
        g_cdfF[base + tid] = (int)excl;
        if (tid == 0) g_cdfF[base + NCF] = PTS;
    }

    // ---- coarse exclusive scan over 128 ----
    unsigned s2 = 0, inc2 = 0;
    if (tid < NCC) {
        s2 = histc[tid]; inc2 = s2;
        #pragma unroll
        for (int o = 1; o < 32; o <<= 1) {
            unsigned n = __shfl_up_sync(FULL, inc2, o);
            if (lane >= o) inc2 += n;
        }
        if (lane == 31) wscanC[wid] = inc2;
    }
    __syncthreads();
    if (tid == 0) {
        unsigned r = 0;
        #pragma unroll
        for (int k = 0; k < 4; k++) { unsigned t = wscanC[k]; wscanC[k] = r; r += t; }
    }
    __syncthreads();
    if (tid < NCC) offsc[tid] = inc2 - s2 + wscanC[wid];
    __syncthreads();

    // ---- pass 3: scatter to fine and coarse orderings (pre-scaled) ----
    float4* __restrict__ dstF = g_fine   + (size_t)(set * BATCH + b) * PTS;
    float4* __restrict__ dstC = g_coarse + (size_t)(set * BATCH + b) * PTS;
    for (int i = tid; i < PTS; i += TPB_B) {
        float x = src[3 * i], y = src[3 * i + 1], z = src[3 * i + 2];
        int cx = (int)fminf(fmaxf((x - x0) * invwx, 0.0f), (float)(NBX - 1));
        int cy = (int)fminf(fmaxf((y - y0) * invwy, 0.0f), (float)(NBY - 1));
        float4 pv = make_float4(-2.0f * x, -2.0f * y, -2.0f * z,
                                fmaf(x, x, fmaf(y, y, z * z)));
        unsigned pF = atomicAdd(&offs[cx * NBY + cy], 1u);
        dstF[pF] = pv;
        unsigned pC = atomicAdd(&offsc[coarse_cell(cx, cy)], 1u);
        dstC[pC] = pv;
    }
}

// ---------------------------------------------------------------------------
// Kernel 2: 2-D windowed NN scan over SMEM-staged targets + SMEM cdf.
// Grid (QTILES, BATCH, 2). dir 0: query=gt, target=pred; dir 1: reverse.
// Phase 1: scan warp-bbox +-1 cell -> per-lane upper bound.
// Phase 2: rescan certified window [bbox +- warp-max d] in x and y.
// ---------------------------------------------------------------------------
__global__ __launch_bounds__(TPB) void chamfer_scan_kernel(float* __restrict__ out)
{
    extern __shared__ float4 st[];          // 4096 staged targets (64KB)
    __shared__ int scdf[NCF + 1];           // 4.1KB

    const int qt = blockIdx.x, b = blockIdx.y, dir = blockIdx.z;
    const int tid = threadIdx.x;
    const unsigned FULL = 0xFFFFFFFFu;
    const int lane = tid & 31;

    const int qset = dir ? 0 : 1;
    const int tset = dir ? 1 : 0;
    const float4* __restrict__ qry = g_coarse + (size_t)(qset * BATCH + b) * PTS;
    const float4* __restrict__ tgt = g_fine   + (size_t)(tset * BATCH + b) * PTS;
    const int*    __restrict__ cdf = g_cdfF + (tset * BATCH + b) * (NCF + 1);

    for (int i = tid; i < PTS; i += TPB) st[i] = __ldg(&tgt[i]);
    for (int i = tid; i < NCF + 1; i += TPB) scdf[i] = __ldg(&cdf[i]);
    __syncthreads();

    const float4 m = __ldg(&g_meta[tset * BATCH + b]);
    const float x0 = m.x, invwx = m.y, y0 = m.z, invwy = m.w;

    const float4 qp = __ldg(&qry[qt * TPB + tid]);
    const float px = -0.5f * qp.x, py = -0.5f * qp.y, pz = -0.5f * qp.z;
    const float p2 = qp.w;

    // Warp bbox of queries.
    float qxl = px, qxh = px, qyl = py, qyh = py;
    #pragma unroll
    for (int o = 16; o > 0; o >>= 1) {
        qxl = fminf(qxl, __shfl_xor_sync(FULL, qxl, o));
        qxh = fmaxf(qxh, __shfl_xor_sync(FULL, qxh, o));
        qyl = fminf(qyl, __shfl_xor_sync(FULL, qyl, o));
        qyh = fmaxf(qyh, __shfl_xor_sync(FULL, qyh, o));
    }

    #define CLX(v) (int)fminf(fmaxf((v), 0.0f), (float)(NBX - 1))
    #define CLY(v) (int)fminf(fmaxf((v), 0.0f), (float)(NBY - 1))

    float bt0 = 3e38f, bt1 = 3e38f, bt2 = 3e38f, bt3 = 3e38f;

    #define BODY(J, ACC) {                                                     \
        float4 g = st[(J)];                                                    \
        ACC = fminf(ACC, fmaf(pz, g.z, fmaf(py, g.y, fmaf(px, g.x, g.w))));    \
    }
    #define SCAN_RANGE(LO, HI) {                                               \
        int j = (LO);                                                          \
        for (; j + 4 <= (HI); j += 4) {                                        \
            BODY(j + 0, bt0) BODY(j + 1, bt1) BODY(j + 2, bt2) BODY(j + 3, bt3)\
        }                                                                      \
        for (; j < (HI); ++j) BODY(j, bt0)                                     \
    }

    // ---- Phase 1: warp bbox +-1 cell ----
    {
        int xl = CLX((qxl - x0) * invwx - 1.0f);
        int xh = CLX((qxh - x0) * invwx + 1.0f);
        int yl = CLY((qyl - y0) * invwy - 1.0f);
        int yh = CLY((qyh - y0) * invwy + 1.0f);
        for (int bx = xl; bx <= xh; ++bx) {
            int s = scdf[bx * NBY + yl];
            int e = scdf[bx * NBY + yh + 1];
            SCAN_RANGE(s, e)
        }
    }

    // ---- Phase 2: certified window from warp-max upper bound ----
    float bt = fminf(fminf(bt0, bt1), fminf(bt2, bt3));
    float d  = sqrtf(fmaxf(bt + p2, 0.0f)) * 1.000002f;
    float dmax = d;
    #pragma unroll
    for (int o = 16; o > 0; o >>= 1)
        dmax = fmaxf(dmax, __shfl_xor_sync(FULL, dmax, o));

    {
        int Xl = CLX(floorf((qxl - dmax - x0) * invwx) - 1.0f);
        int Xh = CLX(floorf((qxh + dmax - x0) * invwx) + 1.0f);
        int Yl = CLY(floorf((qyl - dmax - y0) * invwy) - 1.0f);
        int Yh = CLY(floorf((qyh + dmax - y0) * invwy) + 1.0f);
        for (int bx = Xl; bx <= Xh; ++bx) {
            int s = scdf[bx * NBY + Yl];
            int e = scdf[bx * NBY + Yh + 1];
            SCAN_RANGE(s, e)
        }
    }
    #undef SCAN_RANGE
    #undef BODY
    #undef CLX
    #undef CLY

    bt = fminf(fminf(bt0, bt1), fminf(bt2, bt3));
    float dist = sqrtf(fmaxf(bt + p2, 1e-12f));

    // ---- Block sum reduction + single atomic into out ----
    #pragma unroll
    for (int o = 16; o > 0; o >>= 1)
        dist += __shfl_down_sync(FULL, dist, o);

    __shared__ float wsum[TPB / 32];
    const int wid = tid >> 5;
    if (lane == 0) wsum[wid] = dist;
    __syncthreads();
    if (tid < TPB / 32) {
        float v = wsum[tid];
        #pragma unroll
        for (int o = (TPB / 32) / 2; o > 0; o >>= 1)
            v += __shfl_down_sync(FULL, v, o, TPB / 32);
        if (tid == 0)
            atomicAdd(out, v * (1.0f / (float)(BATCH * PTS)));
    }
}

extern "C" void kernel_launch(void* const* d_in, const int* in_sizes, int n_in,
                              void* d_out, int out_size)
{
    (void)in_sizes; (void)n_in; (void)out_size;
    const float* pred = (const float*)d_in[0];
    const float* gt   = (const float*)d_in[1];
    float* out        = (float*)d_out;

    cudaFuncSetAttribute(chamfer_scan_kernel,
                         cudaFuncAttributeMaxDynamicSharedMemorySize, SMEM_SCAN);

    dim3 bgrid(BATCH, 2);
    build_kernel<<<bgrid, TPB_B>>>(pred, gt, out);

    dim3 sgrid(QTILES, BATCH, 2);
    chamfer_scan_kernel<<<sgrid, TPB, SMEM_SCAN>>>(out);
}

// round 10
// speedup vs baseline: 2.1817x; 1.1984x over previous
#include <cuda_runtime.h>
#include <math.h>

#define PTS    4096
#define BATCH  32
#define NBX    32
#define NBY    32
#define NCF    (NBX * NBY)              // 1024 fine cells (~4 pts/cell)
#define NCC    128                      // 16x8 coarse cells (queries)
#define TPB    256
#define TPB_B  1024
#define QTILES (PTS / TPB)              // 16
#define SMEM_SCAN (PTS * 16)            // 64KB dynamic: staged targets

// Fine-ordered targets in PAIR-PACKED form: pair j occupies float4 2j,2j+1:
//   {-2x0,-2x1,-2y0,-2y1} {-2z0,-2z1, g2_0, g2_1}
__device__ float4 g_fine  [2 * BATCH * PTS];
// Coarse-ordered queries, scaled {-2x,-2y,-2z,|p|^2}.
__device__ float4 g_coarse[2 * BATCH * PTS];
__device__ int    g_cdfF  [2 * BATCH * (NCF + 1)];
__device__ float4 g_meta  [2 * BATCH];   // {x0, invwx, y0, invwy}

__device__ __forceinline__ int coarse_cell(int cx, int cy) {
    int cx2 = cx >> 1, cy2 = cy >> 2;    // 16 x 8
    cy2 = (cx2 & 1) ? (7 - cy2) : cy2;   // serpentine
    return cx2 * 8 + cy2;
}

// ---- Blackwell packed f32x2 helpers ----------------------------------------
__device__ __forceinline__ unsigned long long splat2(float v) {
    unsigned long long r;
    asm("mov.b64 %0, {%1, %1};" : "=l"(r) : "f"(v));
    return r;
}
__device__ __forceinline__ unsigned long long fma2(unsigned long long a,
                                                   unsigned long long b,
                                                   unsigned long long c) {
    unsigned long long d;
    asm("fma.rn.f32x2 %0, %1, %2, %3;" : "=l"(d) : "l"(a), "l"(b), "l"(c));
    return d;
}
__device__ __forceinline__ void min2_acc(unsigned long long t, float& a0, float& a1) {
    float lo, hi;
    asm("mov.b64 {%0, %1}, %2;" : "=f"(lo), "=f"(hi) : "l"(t));
    a0 = fminf(a0, lo);
    a1 = fminf(a1, hi);
}

// ---------------------------------------------------------------------------
// Kernel 1: per (batch,set) 2-D counting sorts. Grid (BATCH, 2), 1024 threads.
// ---------------------------------------------------------------------------
__global__ __launch_bounds__(TPB_B) void build_kernel(
    const float* __restrict__ pred, const float* __restrict__ gt,
    float* __restrict__ out)
{
    __shared__ unsigned hist[NCF];
    __shared__ unsigned offs[NCF];
    __shared__ unsigned histc[NCC];
    __shared__ unsigned offsc[NCC];
    __shared__ unsigned wscan[32];
    __shared__ unsigned wscanC[4];
    __shared__ float    red[128];
    __shared__ float    sm[4];

    const int b = blockIdx.x, set = blockIdx.y, tid = threadIdx.x;
    const int lane = tid & 31, wid = tid >> 5;
    const unsigned FULL = 0xFFFFFFFFu;

    if (b == 0 && set == 0 && tid == 0) out[0] = 0.0f;

    const float* __restrict__ src = (set ? gt : pred) + (size_t)b * PTS * 3;

    // ---- pass 1: bbox of (x, y) ----
    float mnx = 3e38f, mxx = -3e38f, mny = 3e38f, mxy = -3e38f;
    for (int i = tid; i < PTS; i += TPB_B) {
        float x = src[3 * i], y = src[3 * i + 1];
        mnx = fminf(mnx, x); mxx = fmaxf(mxx, x);
        mny = fminf(mny, y); mxy = fmaxf(mxy, y);
    }
    #pragma unroll
    for (int o = 16; o > 0; o >>= 1) {
        mnx = fminf(mnx, __shfl_xor_sync(FULL, mnx, o));
        mxx = fmaxf(mxx, __shfl_xor_sync(FULL, mxx, o));
        mny = fminf(mny, __shfl_xor_sync(FULL, mny, o));
        mxy = fmaxf(mxy, __shfl_xor_sync(FULL, mxy, o));
    }
    if (lane == 0) { red[wid] = mnx; red[32 + wid] = mxx; red[64 + wid] = mny; red[96 + wid] = mxy; }
    if (tid < NCF) hist[tid] = 0;
    if (tid < NCC) histc[tid] = 0;
    __syncthreads();
    if (tid == 0) {
        float a = red[0], c = red[32], e = red[64], f = red[96];
        #pragma unroll
        for (int i = 1; i < 32; i++) {
            a = fminf(a, red[i]);      c = fmaxf(c, red[32 + i]);
            e = fminf(e, red[64 + i]); f = fmaxf(f, red[96 + i]);
        }
        sm[0] = a; sm[1] = (float)NBX / fmaxf(c - a, 1e-30f);
        sm[2] = e; sm[3] = (float)NBY / fmaxf(f - e, 1e-30f);
        g_meta[set * BATCH + b] = make_float4(sm[0], sm[1], sm[2], sm[3]);
    }
    __syncthreads();
    const float x0 = sm[0], invwx = sm[1], y0 = sm[2], invwy = sm[3];

    // ---- pass 2: fine + coarse histograms ----
    for (int i = tid; i < PTS; i += TPB_B) {
        float x = src[3 * i], y = src[3 * i + 1];
        int cx = (int)fminf(fmaxf((x - x0) * invwx, 0.0f), (float)(NBX - 1));
        int cy = (int)fminf(fmaxf((y - y0) * invwy, 0.0f), (float)(NBY - 1));
        atomicAdd(&hist[cx * NBY + cy], 1u);
        atomicAdd(&histc[coarse_cell(cx, cy)], 1u);
    }
    __syncthreads();

    // ---- fine exclusive scan over 1024 ----
    unsigned v = (tid < NCF) ? hist[tid] : 0u;
    unsigned inc = v;
    #pragma unroll
    for (int o = 1; o < 32; o <<= 1) {
        unsigned n = __shfl_up_sync(FULL, inc, o);
        if (lane >= o) inc += n;
    }
    if (lane == 31) wscan[wid] = inc;
    __syncthreads();
    if (wid == 0) {
        unsigned wv = wscan[lane];
        #pragma unroll
        for (int o = 1; o < 32; o <<= 1) {
            unsigned n = __shfl_up_sync(FULL, wv, o);
            if (lane >= o) wv += n;
        }
        wscan[lane] = wv;
    }
    __syncthreads();
    const int base = (set * BATCH + b) * (NCF + 1);
    if (tid < NCF) {
        unsigned excl = inc - v + (wid ? wscan[wid - 1] : 0u);
        offs[tid] = excl;
        g_cdfF[base + tid] = (int)excl;
        if (tid == 0) g_cdfF[base + NCF] = PTS;
    }

    // ---- coarse exclusive scan over 128 ----
    unsigned s2 = 0, inc2 = 0;
    if (tid < NCC) {
        s2 = histc[tid]; inc2 = s2;
        #pragma unroll
        for (int o = 1; o < 32; o <<= 1) {
            unsigned n = __shfl_up_sync(FULL, inc2, o);
            if (lane >= o) inc2 += n;
        }
        if (lane == 31) wscanC[wid] = inc2;
    }
    __syncthreads();
    if (tid == 0) {
        unsigned r = 0;
        #pragma unroll
        for (int k = 0; k < 4; k++) { unsigned t = wscanC[k]; wscanC[k] = r; r += t; }
    }
    __syncthreads();
    if (tid < NCC) offsc[tid] = inc2 - s2 + wscanC[wid];
    __syncthreads();

    // ---- pass 3: scatter. Fine: PAIR-PACKED; coarse: plain float4 ----
    float* __restrict__ dstF = (float*)(g_fine + (size_t)(set * BATCH + b) * PTS);
    float4* __restrict__ dstC = g_coarse + (size_t)(set * BATCH + b) * PTS;
    for (int i = tid; i < PTS; i += TPB_B) {
        float x = src[3 * i], y = src[3 * i + 1], z = src[3 * i + 2];
        int cx = (int)fminf(fmaxf((x - x0) * invwx, 0.0f), (float)(NBX - 1));
        int cy = (int)fminf(fmaxf((y - y0) * invwy, 0.0f), (float)(NBY - 1));
        float g2 = fmaf(x, x, fmaf(y, y, z * z));
        unsigned pF = atomicAdd(&offs[cx * NBY + cy], 1u);
        float* df = dstF + (size_t)(pF >> 1) * 8 + (pF & 1);
        df[0] = -2.0f * x; df[2] = -2.0f * y; df[4] = -2.0f * z; df[6] = g2;
        unsigned pC = atomicAdd(&offsc[coarse_cell(cx, cy)], 1u);
        dstC[pC] = make_float4(-2.0f * x, -2.0f * y, -2.0f * z, g2);
    }
}

// ---------------------------------------------------------------------------
// Kernel 2: ring-expansion NN scan over SMEM-staged pair-packed targets.
// Grid (QTILES, BATCH, 2). dir 0: query=gt,target=pred; dir 1: reverse.
// Scan warp-bbox cells, then grow one ring per iteration; each lane certifies
// when best d <= distance to scanned-rect boundary. All ranges warp-uniform.
// ---------------------------------------------------------------------------
__global__ __launch_bounds__(TPB) void chamfer_scan_kernel(float* __restrict__ out)
{
    extern __shared__ float4 st[];          // 4096 float4 = 2048 packed pairs
    __shared__ int scdf[NCF + 1];

    const int qt = blockIdx.x, b = blockIdx.y, dir = blockIdx.z;
    const int tid = threadIdx.x;
    const unsigned FULL = 0xFFFFFFFFu;
    const int lane = tid & 31;

    const int qset = dir ? 0 : 1;
    const int tset = dir ? 1 : 0;
    const float4* __restrict__ qry = g_coarse + (size_t)(qset * BATCH + b) * PTS;
    const float4* __restrict__ tgt = g_fine   + (size_t)(tset * BATCH + b) * PTS;
    const int*    __restrict__ cdf = g_cdfF + (tset * BATCH + b) * (NCF + 1);

    for (int i = tid; i < PTS; i += TPB) st[i] = __ldg(&tgt[i]);
    for (int i = tid; i < NCF + 1; i += TPB) scdf[i] = __ldg(&cdf[i]);
    __syncthreads();

    const float4 m = __ldg(&g_meta[tset * BATCH + b]);
    const float x0 = m.x, invwx = m.y, y0 = m.z, invwy = m.w;
    const float wx = 1.0f / invwx, wy = 1.0f / invwy;

    const float4 qp = __ldg(&qry[qt * TPB + tid]);
    const float px = -0.5f * qp.x, py = -0.5f * qp.y, pz = -0.5f * qp.z;
    const float p2 = qp.w;
    const unsigned long long sqx = splat2(qp.x * -0.5f),
                             sqy = splat2(qp.y * -0.5f),
                             sqz = splat2(qp.z * -0.5f);

    // Warp bbox of queries.
    float qxl = px, qxh = px, qyl = py, qyh = py;
    #pragma unroll
    for (int o = 16; o > 0; o >>= 1) {
        qxl = fminf(qxl, __shfl_xor_sync(FULL, qxl, o));
        qxh = fmaxf(qxh, __shfl_xor_sync(FULL, qxh, o));
        qyl = fminf(qyl, __shfl_xor_sync(FULL, qyl, o));
        qyh = fmaxf(qyh, __shfl_xor_sync(FULL, qyh, o));
    }

    float bt0 = 3e38f, bt1 = 3e38f;
    const ulonglong2* __restrict__ sp = (const ulonglong2*)st;

    // Pair-rounded scan of point range [LO, HI): superset scan is exact.
    #define SCAN_RANGE(LO, HI) {                                               \
        int jp = (LO) >> 1, je = ((HI) + 1) >> 1;                              \
        for (; jp < je; ++jp) {                                                \
            ulonglong2 u0 = sp[2 * jp];                                        \
            ulonglong2 u1 = sp[2 * jp + 1];                                    \
            unsigned long long t =                                             \
                fma2(sqz, u1.x, fma2(sqy, u0.y, fma2(sqx, u0.x, u1.y)));       \
            min2_acc(t, bt0, bt1);                                             \
        }                                                                      \
    }
    #define SCAN_COL(BX, YA, YB) {                                             \
        int s_ = scdf[(BX) * NBY + (YA)];                                      \
        int e_ = scdf[(BX) * NBY + (YB) + 1];                                  \
        SCAN_RANGE(s_, e_)                                                     \
    }

    // ---- Ring 0: warp bbox cells ----
    int cXl = (int)fminf(fmaxf((qxl - x0) * invwx, 0.0f), (float)(NBX - 1));
    int cXh = (int)fminf(fmaxf((qxh - x0) * invwx, 0.0f), (float)(NBX - 1));
    int cYl = (int)fminf(fmaxf((qyl - y0) * invwy, 0.0f), (float)(NBY - 1));
    int cYh = (int)fminf(fmaxf((qyh - y0) * invwy, 0.0f), (float)(NBY - 1));
    for (int bx = cXl; bx <= cXh; ++bx) SCAN_COL(bx, cYl, cYh)

    // ---- Ring expansion ----
    for (;;) {
        float bt = fminf(bt0, bt1);
        float dbest = sqrtf(fmaxf(bt + p2, 0.0f)) * 1.000002f + 1e-5f;
        float db = 3e38f;
        if (cXl > 0)       db = fminf(db, px - (x0 + (float)cXl * wx));
        if (cXh < NBX - 1) db = fminf(db, (x0 + (float)(cXh + 1) * wx) - px);
        if (cYl > 0)       db = fminf(db, py - (y0 + (float)cYl * wy));
        if (cYh < NBY - 1) db = fminf(db, (y0 + (float)(cYh + 1) * wy) - py);
        if (__all_sync(FULL, dbest <= db)) break;

        int nXl = max(cXl - 1, 0), nXh = min(cXh + 1, NBX - 1);
        int nYl = max(cYl - 1, 0), nYh = min(cYh + 1, NBY - 1);
        if (nXl < cXl) SCAN_COL(nXl, nYl, nYh)
        if (nXh > cXh) SCAN_COL(nXh, nYl, nYh)
        for (int bx = cXl; bx <= cXh; ++bx) {
            if (nYl < cYl) SCAN_COL(bx, nYl, cYl - 1)
            if (nYh > cYh) SCAN_COL(bx, cYh + 1, nYh)
        }
        cXl = nXl; cXh = nXh; cYl = nYl; cYh = nYh;
    }
    #undef SCAN_COL
    #undef SCAN_RANGE

    float bt = fminf(bt0, bt1);
    float dist = sqrtf(fmaxf(bt + p2, 1e-12f));

    // ---- Block sum reduction + single atomic into out ----
    #pragma unroll
    for (int o = 16; o > 0; o >>= 1)
        dist += __shfl_down_sync(FULL, dist, o);

    __shared__ float wsum[TPB / 32];
    const int wid = tid >> 5;
    if (lane == 0) wsum[wid] = dist;
    __syncthreads();
    if (tid < TPB / 32) {
        float v = wsum[tid];
        #pragma unroll
        for (int o = (TPB / 32) / 2; o > 0; o >>= 1)
            v += __shfl_down_sync(FULL, v, o, TPB / 32);
        if (tid == 0)
            atomicAdd(out, v * (1.0f / (float)(BATCH * PTS)));
    }
}

extern "C" void kernel_launch(void* const* d_in, const int* in_sizes, int n_in,
                              void* d_out, int out_size)
{
    (void)in_sizes; (void)n_in; (void)out_size;
    const float* pred = (const float*)d_in[0];
    const float* gt   = (const float*)d_in[1];
    float* out        = (float*)d_out;

    cudaFuncSetAttribute(chamfer_scan_kernel,
                         cudaFuncAttributeMaxDynamicSharedMemorySize, SMEM_SCAN);

    dim3 bgrid(BATCH, 2);
    build_kernel<<<bgrid, TPB_B>>>(pred, gt, out);

    dim3 sgrid(QTILES, BATCH, 2);
    chamfer_scan_kernel<<<sgrid, TPB, SMEM_SCAN>>>(out);
}